// round 2
// baseline (speedup 1.0000x reference)
#include <cuda_runtime.h>
#include <cuda_bf16.h>

// SurfEval fused kernel.
// B=16, M=N=64, deg=3, OUT=256x256, out dim 3 (ctrl has 4 ch, w unused).
// Reference quirks preserved:
//   * V basis is built from knot_u (knot_v is a dead input).
//   * span = argmin over cand = (t-K[3+s] > 1e-8) ? d : 1.0, first-min tie-break.
//   * Cox-de Boor denominator written as (K1 - t) + (t - K2).
//
// Factorization: surf(u,v) = sum_l nu[l] * S_{iu0+l}(v),
//                S_m(v)    = sum_r nv[r] * ctrl[m][iv0(v)+r]
// Thread = fixed v; iterates TILE_U consecutive u rows keeping a 4-entry
// sliding window of S_m in registers (ring indexed by m & 3). Each ctrl row's
// S is computed once per thread instead of once per (u,row) pair.

#define BSZ    16
#define MC     64
#define NC     64
#define DEG    3
#define LK     (MC + DEG + 1)   // 68
#define OUTN   256
#define TILE_U 16               // grid.x = OUTN/TILE_U = 16

// dynamic smem: float4 c4[MC*NC] = 64 KB (full row space; only the needed
// span range is actually loaded, addressed by absolute row index)
extern __shared__ float4 c4[];

__device__ __forceinline__ float param_t(int idx)
{
    const float step = (1.0f - 2e-5f) / (float)(OUTN - 1);
    return 1e-5f + (float)idx * step;
}

// find_span + Cox-de Boor (deg 3), faithful to the reference expressions.
__device__ __forceinline__ void basis_at(float t, const float* __restrict__ U,
                                         float nb[4], int* span_out)
{
    float best = 1.0f;
    int bs = 0;
    #pragma unroll 1
    for (int s = 0; s < LK - 2 * DEG; s++) {
        const float d = t - U[DEG + s];
        const float cand = (d > 1e-8f) ? d : 1.0f;
        if (cand < best) { best = cand; bs = s; }     // strict < = first min
    }
    const int span = bs + DEG;

    nb[0] = 1.0f; nb[1] = 0.f; nb[2] = 0.f; nb[3] = 0.f;
    #pragma unroll
    for (int k = 1; k <= DEG; k++) {
        float saved = 0.0f;
        #pragma unroll
        for (int r = 0; r < k; r++) {
            const float K1 = U[span + r + 1];
            const float K2 = U[span + 1 - k + r];
            const float temp = nb[r] / ((K1 - t) + (t - K2));
            nb[r] = saved + (K1 - t) * temp;
            saved = (t - K2) * temp;
        }
        nb[k] = saved;
    }
    *span_out = span;
}

__global__ __launch_bounds__(256)
void surfeval_fused(const float4* __restrict__ ctrl,
                    const float*  __restrict__ knot_u,
                    float* __restrict__ out)
{
    __shared__ float U[LK];
    __shared__ float nub[TILE_U][4];
    __shared__ int   ius[TILE_U];
    __shared__ int   mlohi[2];

    const int b   = blockIdx.y;
    const int u0  = blockIdx.x * TILE_U;
    const int tid = threadIdx.x;          // = v

    // ---- normalized knots (thread 0; loads pipeline, adds are cheap) ----
    if (tid == 0) {
        float cs[LK];
        float c = 0.f;
        #pragma unroll 1
        for (int i = 0; i < LK; i++) { c += knot_u[b * LK + i]; cs[i] = c; }
        const float c0  = cs[0];
        const float inv = 1.0f / (cs[LK - 1] - c0);
        #pragma unroll 1
        for (int i = 0; i < LK; i++) U[i] = (cs[i] - c0) * inv;
    }
    __syncthreads();

    // ---- basis for this thread's v ----
    float nv[4]; int vspan;
    basis_at(param_t(tid), U, nv, &vspan);
    const int iv0 = vspan - DEG;

    // ---- basis for the tile's u rows (threads 0..TILE_U-1) ----
    if (tid < TILE_U) {
        float nb[4]; int sp;
        basis_at(param_t(u0 + tid), U, nb, &sp);
        ius[tid] = sp - DEG;
        #pragma unroll
        for (int l = 0; l < 4; l++) nub[tid][l] = nb[l];
    }
    __syncthreads();

    if (tid == 0) {
        int lo = ius[0], hi = ius[0];
        #pragma unroll
        for (int i = 1; i < TILE_U; i++) {
            lo = min(lo, ius[i]); hi = max(hi, ius[i]);
        }
        mlohi[0] = lo; mlohi[1] = hi + DEG;
    }
    __syncthreads();

    // ---- cooperative load of the needed ctrl rows (absolute row index) ----
    const int mlo = mlohi[0];
    const int nrows = mlohi[1] - mlo + 1;
    for (int idx = tid; idx < nrows * NC; idx += 256) {
        const int r = idx >> 6;
        const int cc = idx & 63;
        c4[(mlo + r) * NC + cc] = ctrl[((size_t)b * MC + mlo + r) * NC + cc];
    }
    __syncthreads();

    // ---- sliding-window evaluation over TILE_U u rows ----
    float3 S0, S1, S2, S3;               // ring slots, slot = m & 3
    int mtop = -8;                       // highest m with S computed

    float* op = out + (((size_t)(b * OUTN + u0) * OUTN) + tid) * 3;

    #pragma unroll 1
    for (int uu = 0; uu < TILE_U; uu++) {
        const int iu0 = ius[uu];
        if (mtop < iu0 - 1 || mtop > iu0 + 3) mtop = iu0 - 1;  // (re)seed window
        while (mtop < iu0 + 3) {
            mtop++;
            float sx = 0.f, sy = 0.f, sz = 0.f;
            #pragma unroll
            for (int r = 0; r < 4; r++) {
                const float4 cp = c4[mtop * NC + iv0 + r];
                sx = fmaf(nv[r], cp.x, sx);
                sy = fmaf(nv[r], cp.y, sy);
                sz = fmaf(nv[r], cp.z, sz);
            }
            const int slot = mtop & 3;
            if      (slot == 0) S0 = make_float3(sx, sy, sz);
            else if (slot == 1) S1 = make_float3(sx, sy, sz);
            else if (slot == 2) S2 = make_float3(sx, sy, sz);
            else                S3 = make_float3(sx, sy, sz);
        }

        // weight for ring slot s is nu[(s - iu0) mod 4]
        const float w0 = nub[uu][(0 - iu0) & 3];
        const float w1 = nub[uu][(1 - iu0) & 3];
        const float w2 = nub[uu][(2 - iu0) & 3];
        const float w3 = nub[uu][(3 - iu0) & 3];

        op[0] = fmaf(w0, S0.x, fmaf(w1, S1.x, fmaf(w2, S2.x, w3 * S3.x)));
        op[1] = fmaf(w0, S0.y, fmaf(w1, S1.y, fmaf(w2, S2.y, w3 * S3.y)));
        op[2] = fmaf(w0, S0.z, fmaf(w1, S1.z, fmaf(w2, S2.z, w3 * S3.z)));
        op += OUTN * 3;
    }
}

// ---------------------------------------------------------------------------
extern "C" void kernel_launch(void* const* d_in, const int* in_sizes, int n_in,
                              void* d_out, int out_size)
{
    const float4* ctrl   = (const float4*)d_in[0];   // [16,64,64,4] f32
    const float*  knot_u = (const float*)d_in[1];    // [16,68] f32
    // d_in[2] (knot_v) unused: reference builds V from knot_u
    float* out = (float*)d_out;                      // [16,256,256,3] f32

    const int smem = MC * NC * (int)sizeof(float4);  // 64 KB dynamic
    cudaFuncSetAttribute(surfeval_fused,
                         cudaFuncAttributeMaxDynamicSharedMemorySize, smem);
    dim3 grid(OUTN / TILE_U, BSZ);
    surfeval_fused<<<grid, 256, smem>>>(ctrl, knot_u, out);
}